// round 14
// baseline (speedup 1.0000x reference)
#include <cuda_runtime.h>
#include <cuda_bf16.h>
#include <cstdint>
#include <cstddef>

#define IN_F    4096
#define OUT_F   4096
#define M_TOTAL 8192
#define EPS 1e-5f

// GEMM tiling (int8 IMMA + dp4a hybrid, 64/64 split, mbarrier pipeline,
// fills issued by dp4a warps so tensor warps are pure mma consumers)
#define BM 128
#define BN 128
#define BK 128
#define STAGES 3
#define NK (IN_F / BK)          // 32
#define THREADS 256             // 4 tensor warps + 4 dp4a warps
#define DROWS 16                // dp4a rows per warp

#define A_STAGE_BYTES (BM * BK)             // 16384
#define B_STAGE_BYTES (BN * BK)             // 16384
#define STAGE_BYTES   (A_STAGE_BYTES + B_STAGE_BYTES)   // 32768
#define SMEM_TILE0    1024                  // mbarriers live in [0,48)
#define SMEM_TOTAL    (SMEM_TILE0 + STAGES * STAGE_BYTES)   // 99328

#define RED_BLOCKS 1024

// ---------------- device scratch (no cudaMalloc allowed) ----------------
__device__ __align__(128) int8_t g_xq[(size_t)M_TOTAL * IN_F];   // 33.5 MB
__device__ __align__(128) int8_t g_wq[(size_t)OUT_F * IN_F];     // 16.7 MB
__device__ float g_part_max[RED_BLOCKS];
__device__ float g_part_sum[RED_BLOCKS];
__device__ float g_alpha;       // gamma * w_scale / 128 (written by quantize block 0)

// ---------------- helpers ----------------
__device__ __forceinline__ uint32_t smem_u32(const void* p) {
    uint32_t a;
    asm("{ .reg .u64 t; cvta.to.shared.u64 t, %1; cvt.u32.u64 %0, t; }" : "=r"(a) : "l"(p));
    return a;
}
__device__ __forceinline__ void cp_async16(uint32_t s, const void* g) {
    asm volatile("cp.async.cg.shared.global [%0], [%1], 16;" :: "r"(s), "l"(g) : "memory");
}
#define SWZ(o) ((o) ^ (((o) >> 3) & 0x70))

// ---- mbarrier primitives ----
__device__ __forceinline__ void mbar_init(uint32_t a, uint32_t cnt) {
    asm volatile("mbarrier.init.shared.b64 [%0], %1;" :: "r"(a), "r"(cnt) : "memory");
}
__device__ __forceinline__ void mbar_arrive(uint32_t a) {
    asm volatile("mbarrier.arrive.shared.b64 _, [%0];" :: "r"(a) : "memory");
}
// .noinc: completion-arrive only (barrier pre-counted via init).
__device__ __forceinline__ void cp_async_mbar_arrive(uint32_t a) {
    asm volatile("cp.async.mbarrier.arrive.noinc.shared.b64 [%0];" :: "r"(a) : "memory");
}
#define MBAR_WAIT(mbar, parity) do {                                              \
    uint32_t _m = (mbar); uint32_t _p = (parity); uint32_t _done;                 \
    asm volatile(                                                                 \
        "{\n\t.reg .pred p;\n\t"                                                  \
        "mbarrier.try_wait.parity.acquire.cta.shared::cta.b64 p, [%1], %2;\n\t"   \
        "selp.b32 %0, 1, 0, p;\n\t}"                                              \
        : "=r"(_done) : "r"(_m), "r"(_p) : "memory");                             \
    if (!_done) {                                                                 \
        asm volatile(                                                             \
            "{\n\t.reg .pred P1;\n\t"                                             \
            "WL_%=:\n\t"                                                          \
            "mbarrier.try_wait.parity.acquire.cta.shared::cta.b64 P1, [%0], %1, 0x989680;\n\t" \
            "@P1 bra.uni WD_%=;\n\t"                                              \
            "bra.uni WL_%=;\n\t"                                                  \
            "WD_%=:\n\t}"                                                         \
            :: "r"(_m), "r"(_p) : "memory");                                      \
    }                                                                             \
} while (0)

__device__ __forceinline__ void ldmatrix_x4(uint32_t& r0, uint32_t& r1, uint32_t& r2,
                                            uint32_t& r3, uint32_t addr) {
    asm volatile("ldmatrix.sync.aligned.m8n8.x4.shared.b16 {%0,%1,%2,%3}, [%4];"
                 : "=r"(r0), "=r"(r1), "=r"(r2), "=r"(r3) : "r"(addr));
}
__device__ __forceinline__ void mma_s8(int& d0, int& d1, int& d2, int& d3,
                                       uint32_t a0, uint32_t a1, uint32_t a2, uint32_t a3,
                                       uint32_t b0, uint32_t b1) {
    asm volatile("mma.sync.aligned.m16n8k32.row.col.s32.s8.s8.s32 "
                 "{%0,%1,%2,%3}, {%4,%5,%6,%7}, {%8,%9}, {%0,%1,%2,%3};"
                 : "+r"(d0), "+r"(d1), "+r"(d2), "+r"(d3)
                 : "r"(a0), "r"(a1), "r"(a2), "r"(a3), "r"(b0), "r"(b1));
}

// ---------------- kernel 1: partial reductions (deterministic, no atomics) ----------------
__global__ void __launch_bounds__(256) reduce_partial_kernel(const float* __restrict__ x,
                                                             const float* __restrict__ w) {
    __shared__ float sred[256];
    int t = threadIdx.x;
    int gid = blockIdx.x * 256 + t;
    int stride = gridDim.x * 256;

    float mx = 0.f;
    const float4* x4 = reinterpret_cast<const float4*>(x);
    const int nx4 = (M_TOTAL * IN_F) / 4;
    for (int i = gid; i < nx4; i += stride) {
        float4 v = x4[i];
        mx = fmaxf(mx, fabsf(v.x)); mx = fmaxf(mx, fabsf(v.y));
        mx = fmaxf(mx, fabsf(v.z)); mx = fmaxf(mx, fabsf(v.w));
    }
    float sm = 0.f;
    const float4* w4 = reinterpret_cast<const float4*>(w);
    const int nw4 = (OUT_F * IN_F) / 4;
    for (int i = gid; i < nw4; i += stride) {
        float4 v = w4[i];
        sm += fabsf(v.x) + fabsf(v.y) + fabsf(v.z) + fabsf(v.w);
    }

    sred[t] = mx; __syncthreads();
    for (int o = 128; o > 0; o >>= 1) { if (t < o) sred[t] = fmaxf(sred[t], sred[t + o]); __syncthreads(); }
    if (t == 0) g_part_max[blockIdx.x] = sred[0];
    __syncthreads();
    sred[t] = sm; __syncthreads();
    for (int o = 128; o > 0; o >>= 1) { if (t < o) sred[t] += sred[t + o]; __syncthreads(); }
    if (t == 0) g_part_sum[blockIdx.x] = sred[0];
}

// ---------------- kernel 2: quantize (finalizes scales redundantly per block) ----------------
__device__ __forceinline__ int pack_q(float a, float b, float c, float d) {
    int ia = (int)a, ib = (int)b, ic = (int)c, id = (int)d;
    return (ia & 255) | ((ib & 255) << 8) | ((ic & 255) << 16) | ((id & 255) << 24);
}

__global__ void __launch_bounds__(256) quantize_kernel(const float4* __restrict__ x4,
                                                       const float4* __restrict__ w4) {
    __shared__ float sred[256];
    const int t = threadIdx.x;

    // redundant per-block finalize of the partials (4 KB from L2)
    float mx = fmaxf(fmaxf(g_part_max[t], g_part_max[t + 256]),
                     fmaxf(g_part_max[t + 512], g_part_max[t + 768]));
    sred[t] = mx; __syncthreads();
    for (int o = 128; o > 0; o >>= 1) { if (t < o) sred[t] = fmaxf(sred[t], sred[t + o]); __syncthreads(); }
    const float gamma = fmaxf(sred[0], EPS);
    __syncthreads();
    float sm = g_part_sum[t] + g_part_sum[t + 256] + g_part_sum[t + 512] + g_part_sum[t + 768];
    sred[t] = sm; __syncthreads();
    for (int o = 128; o > 0; o >>= 1) { if (t < o) sred[t] += sred[t + o]; __syncthreads(); }
    const float wsc = fmaxf(sred[0] * (1.0f / ((float)OUT_F * (float)IN_F)), EPS);

    if (blockIdx.x == 0 && t == 0)
        g_alpha = gamma * wsc * (1.0f / 128.0f);

    const float sx = 128.0f / gamma;
    int gid = blockIdx.x * blockDim.x + t;
    int nt = gridDim.x * blockDim.x;

    int* xq = reinterpret_cast<int*>(g_xq);
    const int nx4 = (M_TOTAL * IN_F) / 4;
    for (int i = gid; i < nx4; i += nt) {
        float4 v = x4[i];
        float a = fminf(fmaxf(rintf(__fmul_rn(v.x, sx)), -128.f), 127.f);
        float b = fminf(fmaxf(rintf(__fmul_rn(v.y, sx)), -128.f), 127.f);
        float c = fminf(fmaxf(rintf(__fmul_rn(v.z, sx)), -128.f), 127.f);
        float d = fminf(fmaxf(rintf(__fmul_rn(v.w, sx)), -128.f), 127.f);
        xq[i] = pack_q(a, b, c, d);
    }
    int* wq = reinterpret_cast<int*>(g_wq);
    const int nw4 = (OUT_F * IN_F) / 4;
    for (int i = gid; i < nw4; i += nt) {
        float4 v = w4[i];
        float a = fminf(fmaxf(rintf(__fdiv_rn(v.x, wsc)), -1.f), 1.f);
        float b = fminf(fmaxf(rintf(__fdiv_rn(v.y, wsc)), -1.f), 1.f);
        float c = fminf(fmaxf(rintf(__fdiv_rn(v.z, wsc)), -1.f), 1.f);
        float d = fminf(fmaxf(rintf(__fdiv_rn(v.w, wsc)), -1.f), 1.f);
        wq[i] = pack_q(a, b, c, d);
    }
}

// ---------------- kernel 3: hybrid IMMA + dp4a GEMM, mbarrier pipeline ----------------
// Fills issued by the 4 dp4a warps (local tid 0..127 within that group).
__device__ __forceinline__ void fill_stage(uint32_t sbase, int slot, int k_iter, int ltid,
                                           const int8_t* gA, const int8_t* gB) {
    const int k0 = k_iter * BK;
    const uint32_t abase = sbase + SMEM_TILE0 + slot * STAGE_BYTES;
    const uint32_t bbase = abase + A_STAGE_BYTES;
#pragma unroll
    for (int i = 0; i < 8; i++) {
        int c = ltid + i * 128;
        int row = c >> 3, cg = c & 7;
        uint32_t off = (uint32_t)(row * 128 + cg * 16);
        cp_async16(abase + SWZ(off), gA + (size_t)row * IN_F + k0 + cg * 16);
    }
#pragma unroll
    for (int i = 0; i < 8; i++) {
        int c = ltid + i * 128;
        int row = c >> 3, cg = c & 7;
        uint32_t off = (uint32_t)(row * 128 + cg * 16);
        cp_async16(bbase + SWZ(off), gB + (size_t)row * IN_F + k0 + cg * 16);
    }
}

__global__ void __launch_bounds__(THREADS, 2) gemm_kernel(const float* __restrict__ bias,
                                                          float* __restrict__ out) {
    extern __shared__ char smem[];
    const uint32_t sbase = smem_u32(smem);
    const int tid = threadIdx.x;
    const int wid = tid >> 5;
    const int l = tid & 31;
    const int n0 = blockIdx.x * BN;
    const int m0 = blockIdx.y * BM;

    // mbarriers: full[s] at sbase+16s (count 128 async arrivals), empty[s] at +8 (count 8 warps)
    if (tid == 0) {
#pragma unroll
        for (int s = 0; s < STAGES; s++) {
            mbar_init(sbase + 16 * s, 128);
            mbar_init(sbase + 16 * s + 8, 8);
        }
    }
    __syncthreads();   // publish mbarrier init (only CTA-wide barrier in the kernel)

    const int8_t* gA = g_xq + (size_t)m0 * IN_F;
    const int8_t* gB = g_wq + (size_t)n0 * IN_F;

    if (wid < 4) {
        // ---------------- tensor warps: rows 0..63, cols wid*32..wid*32+31 ----------------
        // Pure consumers: no cp.async duty at all.
        const int warp_n = wid;

        int acc[4][4][4];
#pragma unroll
        for (int a = 0; a < 4; a++)
#pragma unroll
            for (int b = 0; b < 4; b++)
#pragma unroll
                for (int c = 0; c < 4; c++) acc[a][b][c] = 0;

        const int am_base = (l & 15);
        const int bn_base = warp_n * 32 + (l & 15);
        const uint32_t colg = (uint32_t)((l >> 4) * 16);
        const uint32_t aswz = (uint32_t)((am_base & 7) * 16);
        const uint32_t bswz = (uint32_t)((bn_base & 7) * 16);

        uint32_t af[2][4][4];
        uint32_t bf[2][2][4];

        int slot = 0, cpar = 0;      // consumer cursor (full barriers)

        for (int k = 0; k < NK; k++) {
            MBAR_WAIT(sbase + 16 * slot, (uint32_t)cpar);   // stage data ready

            const uint32_t sA = sbase + SMEM_TILE0 + slot * STAGE_BYTES;
            const uint32_t sB = sA + A_STAGE_BYTES;
            const uint32_t aAddr = sA + (uint32_t)am_base * 128;
            const uint32_t bAddr = sB + (uint32_t)bn_base * 128;

            // prefetch ks=0 frags
            {
                const uint32_t acol = colg ^ aswz;
                const uint32_t bcol = colg ^ bswz;
#pragma unroll
                for (int mt = 0; mt < 4; mt++)
                    ldmatrix_x4(af[0][mt][0], af[0][mt][1], af[0][mt][2], af[0][mt][3],
                                aAddr + (uint32_t)(mt * 16 * 128) + acol);
#pragma unroll
                for (int nh = 0; nh < 2; nh++)
                    ldmatrix_x4(bf[0][nh][0], bf[0][nh][1], bf[0][nh][2], bf[0][nh][3],
                                bAddr + (uint32_t)(nh * 16 * 128) + bcol);
            }

#pragma unroll
            for (int ks = 0; ks < BK / 32; ks++) {
                const int cur = ks & 1;
                const int nxt = cur ^ 1;
                if (ks < BK / 32 - 1) {
                    const uint32_t acol = ((uint32_t)((ks + 1) * 32) + colg) ^ aswz;
                    const uint32_t bcol = ((uint32_t)((ks + 1) * 32) + colg) ^ bswz;
#pragma unroll
                    for (int mt = 0; mt < 4; mt++)
                        ldmatrix_x4(af[nxt][mt][0], af[nxt][mt][1], af[nxt][mt][2], af[nxt][mt][3],
                                    aAddr + (uint32_t)(mt * 16 * 128) + acol);
#pragma unroll
                    for (int nh = 0; nh < 2; nh++)
                        ldmatrix_x4(bf[nxt][nh][0], bf[nxt][nh][1], bf[nxt][nh][2], bf[nxt][nh][3],
                                    bAddr + (uint32_t)(nh * 16 * 128) + bcol);
                }
#pragma unroll
                for (int mt = 0; mt < 4; mt++)
#pragma unroll
                    for (int nt = 0; nt < 4; nt++) {
                        const int nh = nt >> 1, sub = nt & 1;
                        mma_s8(acc[mt][nt][0], acc[mt][nt][1], acc[mt][nt][2], acc[mt][nt][3],
                               af[cur][mt][0], af[cur][mt][1], af[cur][mt][2], af[cur][mt][3],
                               bf[cur][nh][sub], bf[cur][nh][sub + 2]);
                    }
            }

            __syncwarp();
            if (l == 0) mbar_arrive(sbase + 16 * slot + 8);   // release stage
            if (++slot == STAGES) { slot = 0; cpar ^= 1; }
        }

        // epilogue
        const float alpha = g_alpha;
        const int row_base = m0 + (l >> 2);
        const int col_base = n0 + warp_n * 32 + (l & 3) * 2;
#pragma unroll
        for (int nt = 0; nt < 4; nt++) {
            const int col = col_base + nt * 8;
            const float2 b2 = *reinterpret_cast<const float2*>(bias + col);
#pragma unroll
            for (int mt = 0; mt < 4; mt++) {
                const int r0 = row_base + mt * 16;
                float2 v0, v1;
                v0.x = __fadd_rn(__fmul_rn(__int2float_rn(acc[mt][nt][0]), alpha), b2.x);
                v0.y = __fadd_rn(__fmul_rn(__int2float_rn(acc[mt][nt][1]), alpha), b2.y);
                v1.x = __fadd_rn(__fmul_rn(__int2float_rn(acc[mt][nt][2]), alpha), b2.x);
                v1.y = __fadd_rn(__fmul_rn(__int2float_rn(acc[mt][nt][3]), alpha), b2.y);
                *reinterpret_cast<float2*>(out + (size_t)r0 * OUT_F + col) = v0;
                *reinterpret_cast<float2*>(out + (size_t)(r0 + 8) * OUT_F + col) = v1;
            }
        }
    } else {
        // ---------------- dp4a warps: rows 64..127 (16 per warp), all 128 cols + fills ----------------
        const int ltid = tid - 128;               // 0..127 within dp4a group
        const int dw = wid - 4;                   // 0..3
        const int arow0 = 64 + DROWS * dw;        // (arow0 & 7) == 0

        // prologue: dp4a warps prefill stages 0,1 (empty barriers start "ready")
        fill_stage(sbase, 0, 0, ltid, gA, gB); cp_async_mbar_arrive(sbase + 0);
        fill_stage(sbase, 1, 1, ltid, gA, gB); cp_async_mbar_arrive(sbase + 16);

        int acc[DROWS][4];
#pragma unroll
        for (int i = 0; i < DROWS; i++)
#pragma unroll
            for (int j = 0; j < 4; j++) acc[i][j] = 0;

        const uint32_t bswz = (uint32_t)((l & 7) * 16);

        int slot = 0, cpar = 0;      // consumer cursor
        int fslot = 2, fpar = 1;     // producer cursor, first fill kn=2

        for (int k = 0; k < NK; k++) {
            MBAR_WAIT(sbase + 16 * slot, (uint32_t)cpar);   // stage data ready

            const char* sAp = smem + SMEM_TILE0 + slot * STAGE_BYTES;
            const char* sBp = sAp + A_STAGE_BYTES;
            const char* aRow = sAp + arow0 * 128;

#pragma unroll 2
            for (int k16 = 0; k16 < BK / 16; k16++) {
                const uint32_t kb16 = (uint32_t)(k16 * 16);
                int4 b4[4];
#pragma unroll
                for (int j = 0; j < 4; j++) {
                    const int brow = l + 32 * j;
                    b4[j] = *reinterpret_cast<const int4*>(sBp + brow * 128 + (kb16 ^ bswz));
                }
#pragma unroll
                for (int i = 0; i < DROWS; i++) {
                    const int4 a4 = *reinterpret_cast<const int4*>(
                        aRow + i * 128 + (kb16 ^ (uint32_t)((i & 7) * 16)));
                    const int* a = reinterpret_cast<const int*>(&a4);
#pragma unroll
                    for (int k4 = 0; k4 < 4; k4++) {
                        acc[i][0] = __dp4a(a[k4], reinterpret_cast<const int*>(&b4[0])[k4], acc[i][0]);
                        acc[i][1] = __dp4a(a[k4], reinterpret_cast<const int*>(&b4[1])[k4], acc[i][1]);
                        acc[i][2] = __dp4a(a[k4], reinterpret_cast<const int*>(&b4[2])[k4], acc[i][2]);
                        acc[i][3] = __dp4a(a[k4], reinterpret_cast<const int*>(&b4[3])[k4], acc[i][3]);
                    }
                }
            }

            __syncwarp();
            if (l == 0) mbar_arrive(sbase + 16 * slot + 8);   // release stage

            const int kn = k + 2;
            if (kn < NK) {   // refill from dp4a warps (issue slots are free here)
                MBAR_WAIT(sbase + 16 * fslot + 8, (uint32_t)fpar);
                fill_stage(sbase, fslot, kn, ltid, gA, gB);
                cp_async_mbar_arrive(sbase + 16 * fslot);
                if (++fslot == STAGES) { fslot = 0; fpar ^= 1; }
            }
            if (++slot == STAGES) { slot = 0; cpar ^= 1; }
        }

        // epilogue
        const float alpha = g_alpha;
#pragma unroll
        for (int j = 0; j < 4; j++) {
            const int col = n0 + l + 32 * j;
            const float bj = bias[col];
#pragma unroll
            for (int i = 0; i < DROWS; i++) {
                const int row = m0 + arow0 + i;
                out[(size_t)row * OUT_F + col] =
                    __fadd_rn(__fmul_rn(__int2float_rn(acc[i][j]), alpha), bj);
            }
        }
    }
}

// ---------------- launch ----------------
extern "C" void kernel_launch(void* const* d_in, const int* in_sizes, int n_in,
                              void* d_out, int out_size) {
    const float* x    = (const float*)d_in[0];
    const float* w    = (const float*)d_in[1];
    const float* bias = (const float*)d_in[2];
    float* out = (float*)d_out;

    reduce_partial_kernel<<<RED_BLOCKS, 256>>>(x, w);
    quantize_kernel<<<2048, 256>>>((const float4*)x, (const float4*)w);

    cudaFuncSetAttribute(gemm_kernel, cudaFuncAttributeMaxDynamicSharedMemorySize, SMEM_TOTAL);
    dim3 grid(OUT_F / BN, M_TOTAL / BM);
    gemm_kernel<<<grid, THREADS, SMEM_TOTAL>>>(bias, out);
}

// round 16
// speedup vs baseline: 1.1190x; 1.1190x over previous
#include <cuda_runtime.h>
#include <cuda_bf16.h>
#include <cstdint>
#include <cstddef>

#define IN_F    4096
#define OUT_F   4096
#define M_TOTAL 8192
#define EPS 1e-5f

// GEMM tiling (int8 IMMA + dp4a hybrid, 64/64 split, mbarrier pipeline,
// fills issued by TENSOR warps — they have issue slack; dp4a pipe is the
// saturated resource and must stay load-free). r13 structure.
#define BM 128
#define BN 128
#define BK 128
#define STAGES 3
#define NK (IN_F / BK)          // 32
#define THREADS 256             // 4 tensor warps + 4 dp4a warps
#define DROWS 16                // dp4a rows per warp

#define A_STAGE_BYTES (BM * BK)             // 16384
#define B_STAGE_BYTES (BN * BK)             // 16384
#define STAGE_BYTES   (A_STAGE_BYTES + B_STAGE_BYTES)   // 32768
#define SMEM_TILE0    1024                  // mbarriers live in [0,48)
#define SMEM_TOTAL    (SMEM_TILE0 + STAGES * STAGE_BYTES)   // 99328

#define RED_BLOCKS 1024

// ---------------- device scratch (no cudaMalloc allowed) ----------------
__device__ __align__(128) int8_t g_xq[(size_t)M_TOTAL * IN_F];   // 33.5 MB
__device__ __align__(128) int8_t g_wq[(size_t)OUT_F * IN_F];     // 16.7 MB
__device__ float g_part_max[RED_BLOCKS];
__device__ float g_part_sum[RED_BLOCKS];
__device__ float g_alpha;       // gamma * w_scale / 128 (written by quantize block 0)

// ---------------- helpers ----------------
__device__ __forceinline__ uint32_t smem_u32(const void* p) {
    uint32_t a;
    asm("{ .reg .u64 t; cvta.to.shared.u64 t, %1; cvt.u32.u64 %0, t; }" : "=r"(a) : "l"(p));
    return a;
}
__device__ __forceinline__ void cp_async16(uint32_t s, const void* g) {
    asm volatile("cp.async.cg.shared.global [%0], [%1], 16;" :: "r"(s), "l"(g) : "memory");
}
#define SWZ(o) ((o) ^ (((o) >> 3) & 0x70))

// ---- mbarrier primitives ----
__device__ __forceinline__ void mbar_init(uint32_t a, uint32_t cnt) {
    asm volatile("mbarrier.init.shared.b64 [%0], %1;" :: "r"(a), "r"(cnt) : "memory");
}
__device__ __forceinline__ void mbar_arrive(uint32_t a) {
    asm volatile("mbarrier.arrive.shared.b64 _, [%0];" :: "r"(a) : "memory");
}
// .noinc: completion-arrive only (barrier pre-counted via init).
__device__ __forceinline__ void cp_async_mbar_arrive(uint32_t a) {
    asm volatile("cp.async.mbarrier.arrive.noinc.shared.b64 [%0];" :: "r"(a) : "memory");
}
#define MBAR_WAIT(mbar, parity) do {                                              \
    uint32_t _m = (mbar); uint32_t _p = (parity); uint32_t _done;                 \
    asm volatile(                                                                 \
        "{\n\t.reg .pred p;\n\t"                                                  \
        "mbarrier.try_wait.parity.acquire.cta.shared::cta.b64 p, [%1], %2;\n\t"   \
        "selp.b32 %0, 1, 0, p;\n\t}"                                              \
        : "=r"(_done) : "r"(_m), "r"(_p) : "memory");                             \
    if (!_done) {                                                                 \
        asm volatile(                                                             \
            "{\n\t.reg .pred P1;\n\t"                                             \
            "WL_%=:\n\t"                                                          \
            "mbarrier.try_wait.parity.acquire.cta.shared::cta.b64 P1, [%0], %1, 0x989680;\n\t" \
            "@P1 bra.uni WD_%=;\n\t"                                              \
            "bra.uni WL_%=;\n\t"                                                  \
            "WD_%=:\n\t}"                                                         \
            :: "r"(_m), "r"(_p) : "memory");                                      \
    }                                                                             \
} while (0)

__device__ __forceinline__ void ldmatrix_x4(uint32_t& r0, uint32_t& r1, uint32_t& r2,
                                            uint32_t& r3, uint32_t addr) {
    asm volatile("ldmatrix.sync.aligned.m8n8.x4.shared.b16 {%0,%1,%2,%3}, [%4];"
                 : "=r"(r0), "=r"(r1), "=r"(r2), "=r"(r3) : "r"(addr));
}
__device__ __forceinline__ void mma_s8(int& d0, int& d1, int& d2, int& d3,
                                       uint32_t a0, uint32_t a1, uint32_t a2, uint32_t a3,
                                       uint32_t b0, uint32_t b1) {
    asm volatile("mma.sync.aligned.m16n8k32.row.col.s32.s8.s8.s32 "
                 "{%0,%1,%2,%3}, {%4,%5,%6,%7}, {%8,%9}, {%0,%1,%2,%3};"
                 : "+r"(d0), "+r"(d1), "+r"(d2), "+r"(d3)
                 : "r"(a0), "r"(a1), "r"(a2), "r"(a3), "r"(b0), "r"(b1));
}

// ---------------- kernel 1: partial reductions (deterministic, no atomics) ----------------
__global__ void __launch_bounds__(256) reduce_partial_kernel(const float* __restrict__ x,
                                                             const float* __restrict__ w) {
    __shared__ float sred[256];
    int t = threadIdx.x;
    int gid = blockIdx.x * 256 + t;
    int stride = gridDim.x * 256;

    float mx = 0.f;
    const float4* x4 = reinterpret_cast<const float4*>(x);
    const int nx4 = (M_TOTAL * IN_F) / 4;
    for (int i = gid; i < nx4; i += stride) {
        float4 v = x4[i];
        mx = fmaxf(mx, fabsf(v.x)); mx = fmaxf(mx, fabsf(v.y));
        mx = fmaxf(mx, fabsf(v.z)); mx = fmaxf(mx, fabsf(v.w));
    }
    float sm = 0.f;
    const float4* w4 = reinterpret_cast<const float4*>(w);
    const int nw4 = (OUT_F * IN_F) / 4;
    for (int i = gid; i < nw4; i += stride) {
        float4 v = w4[i];
        sm += fabsf(v.x) + fabsf(v.y) + fabsf(v.z) + fabsf(v.w);
    }

    sred[t] = mx; __syncthreads();
    for (int o = 128; o > 0; o >>= 1) { if (t < o) sred[t] = fmaxf(sred[t], sred[t + o]); __syncthreads(); }
    if (t == 0) g_part_max[blockIdx.x] = sred[0];
    __syncthreads();
    sred[t] = sm; __syncthreads();
    for (int o = 128; o > 0; o >>= 1) { if (t < o) sred[t] += sred[t + o]; __syncthreads(); }
    if (t == 0) g_part_sum[blockIdx.x] = sred[0];
}

// ---------------- kernel 2: quantize (finalizes scales redundantly per block) ----------------
__device__ __forceinline__ int pack_q(float a, float b, float c, float d) {
    int ia = (int)a, ib = (int)b, ic = (int)c, id = (int)d;
    return (ia & 255) | ((ib & 255) << 8) | ((ic & 255) << 16) | ((id & 255) << 24);
}

__global__ void __launch_bounds__(256) quantize_kernel(const float4* __restrict__ x4,
                                                       const float4* __restrict__ w4) {
    __shared__ float sred[256];
    const int t = threadIdx.x;

    // redundant per-block finalize of the partials (4 KB from L2)
    float mx = fmaxf(fmaxf(g_part_max[t], g_part_max[t + 256]),
                     fmaxf(g_part_max[t + 512], g_part_max[t + 768]));
    sred[t] = mx; __syncthreads();
    for (int o = 128; o > 0; o >>= 1) { if (t < o) sred[t] = fmaxf(sred[t], sred[t + o]); __syncthreads(); }
    const float gamma = fmaxf(sred[0], EPS);
    __syncthreads();
    float sm = g_part_sum[t] + g_part_sum[t + 256] + g_part_sum[t + 512] + g_part_sum[t + 768];
    sred[t] = sm; __syncthreads();
    for (int o = 128; o > 0; o >>= 1) { if (t < o) sred[t] += sred[t + o]; __syncthreads(); }
    const float wsc = fmaxf(sred[0] * (1.0f / ((float)OUT_F * (float)IN_F)), EPS);

    if (blockIdx.x == 0 && t == 0)
        g_alpha = gamma * wsc * (1.0f / 128.0f);

    const float sx = 128.0f / gamma;
    int gid = blockIdx.x * blockDim.x + t;
    int nt = gridDim.x * blockDim.x;

    int* xq = reinterpret_cast<int*>(g_xq);
    const int nx4 = (M_TOTAL * IN_F) / 4;
    for (int i = gid; i < nx4; i += nt) {
        float4 v = x4[i];
        float a = fminf(fmaxf(rintf(__fmul_rn(v.x, sx)), -128.f), 127.f);
        float b = fminf(fmaxf(rintf(__fmul_rn(v.y, sx)), -128.f), 127.f);
        float c = fminf(fmaxf(rintf(__fmul_rn(v.z, sx)), -128.f), 127.f);
        float d = fminf(fmaxf(rintf(__fmul_rn(v.w, sx)), -128.f), 127.f);
        xq[i] = pack_q(a, b, c, d);
    }
    int* wq = reinterpret_cast<int*>(g_wq);
    const int nw4 = (OUT_F * IN_F) / 4;
    for (int i = gid; i < nw4; i += nt) {
        float4 v = w4[i];
        float a = fminf(fmaxf(rintf(__fdiv_rn(v.x, wsc)), -1.f), 1.f);
        float b = fminf(fmaxf(rintf(__fdiv_rn(v.y, wsc)), -1.f), 1.f);
        float c = fminf(fmaxf(rintf(__fdiv_rn(v.z, wsc)), -1.f), 1.f);
        float d = fminf(fmaxf(rintf(__fdiv_rn(v.w, wsc)), -1.f), 1.f);
        wq[i] = pack_q(a, b, c, d);
    }
}

// ---------------- kernel 3: hybrid IMMA + dp4a GEMM, mbarrier pipeline (r13) ----------------
// Loads done by the 4 tensor warps only (threads 0..127, 16 chunks each).
__device__ __forceinline__ void fill_stage(uint32_t sbase, int slot, int k_iter, int tid,
                                           const int8_t* gA, const int8_t* gB) {
    const int k0 = k_iter * BK;
    const uint32_t abase = sbase + SMEM_TILE0 + slot * STAGE_BYTES;
    const uint32_t bbase = abase + A_STAGE_BYTES;
#pragma unroll
    for (int i = 0; i < 8; i++) {
        int c = tid + i * 128;
        int row = c >> 3, cg = c & 7;
        uint32_t off = (uint32_t)(row * 128 + cg * 16);
        cp_async16(abase + SWZ(off), gA + (size_t)row * IN_F + k0 + cg * 16);
    }
#pragma unroll
    for (int i = 0; i < 8; i++) {
        int c = tid + i * 128;
        int row = c >> 3, cg = c & 7;
        uint32_t off = (uint32_t)(row * 128 + cg * 16);
        cp_async16(bbase + SWZ(off), gB + (size_t)row * IN_F + k0 + cg * 16);
    }
}

__global__ void __launch_bounds__(THREADS, 2) gemm_kernel(const float* __restrict__ bias,
                                                          float* __restrict__ out) {
    extern __shared__ char smem[];
    const uint32_t sbase = smem_u32(smem);
    const int tid = threadIdx.x;
    const int wid = tid >> 5;
    const int l = tid & 31;
    const int n0 = blockIdx.x * BN;
    const int m0 = blockIdx.y * BM;

    // mbarriers: full[s] at sbase+16s (count 128 async arrivals), empty[s] at +8 (count 8 warps)
    if (tid == 0) {
#pragma unroll
        for (int s = 0; s < STAGES; s++) {
            mbar_init(sbase + 16 * s, 128);
            mbar_init(sbase + 16 * s + 8, 8);
        }
    }
    __syncthreads();   // publish mbarrier init (only CTA-wide barrier in the kernel)

    const int8_t* gA = g_xq + (size_t)m0 * IN_F;
    const int8_t* gB = g_wq + (size_t)n0 * IN_F;

    // prologue: tensor warps prefill stages 0,1 (empty barriers start "ready")
    if (wid < 4) {
        fill_stage(sbase, 0, 0, tid, gA, gB); cp_async_mbar_arrive(sbase + 0);
        fill_stage(sbase, 1, 1, tid, gA, gB); cp_async_mbar_arrive(sbase + 16);
    }

    if (wid < 4) {
        // ---------------- tensor warps: rows 0..63, cols wid*32..wid*32+31 ----------------
        const int warp_n = wid;

        int acc[4][4][4];
#pragma unroll
        for (int a = 0; a < 4; a++)
#pragma unroll
            for (int b = 0; b < 4; b++)
#pragma unroll
                for (int c = 0; c < 4; c++) acc[a][b][c] = 0;

        const int am_base = (l & 15);
        const int bn_base = warp_n * 32 + (l & 15);
        const uint32_t colg = (uint32_t)((l >> 4) * 16);
        const uint32_t aswz = (uint32_t)((am_base & 7) * 16);
        const uint32_t bswz = (uint32_t)((bn_base & 7) * 16);

        uint32_t af[2][4][4];
        uint32_t bf[2][2][4];

        int slot = 0, cpar = 0;      // consumer cursor (full barriers)
        int fslot = 2, fpar = 1;     // producer cursor (empty barriers), first fill kn=2

        for (int k = 0; k < NK; k++) {
            MBAR_WAIT(sbase + 16 * slot, (uint32_t)cpar);   // stage data ready

            const uint32_t sA = sbase + SMEM_TILE0 + slot * STAGE_BYTES;
            const uint32_t sB = sA + A_STAGE_BYTES;
            const uint32_t aAddr = sA + (uint32_t)am_base * 128;
            const uint32_t bAddr = sB + (uint32_t)bn_base * 128;

            // prefetch ks=0 frags
            {
                const uint32_t acol = colg ^ aswz;
                const uint32_t bcol = colg ^ bswz;
#pragma unroll
                for (int mt = 0; mt < 4; mt++)
                    ldmatrix_x4(af[0][mt][0], af[0][mt][1], af[0][mt][2], af[0][mt][3],
                                aAddr + (uint32_t)(mt * 16 * 128) + acol);
#pragma unroll
                for (int nh = 0; nh < 2; nh++)
                    ldmatrix_x4(bf[0][nh][0], bf[0][nh][1], bf[0][nh][2], bf[0][nh][3],
                                bAddr + (uint32_t)(nh * 16 * 128) + bcol);
            }

#pragma unroll
            for (int ks = 0; ks < BK / 32; ks++) {
                const int cur = ks & 1;
                const int nxt = cur ^ 1;
                if (ks < BK / 32 - 1) {
                    const uint32_t acol = ((uint32_t)((ks + 1) * 32) + colg) ^ aswz;
                    const uint32_t bcol = ((uint32_t)((ks + 1) * 32) + colg) ^ bswz;
#pragma unroll
                    for (int mt = 0; mt < 4; mt++)
                        ldmatrix_x4(af[nxt][mt][0], af[nxt][mt][1], af[nxt][mt][2], af[nxt][mt][3],
                                    aAddr + (uint32_t)(mt * 16 * 128) + acol);
#pragma unroll
                    for (int nh = 0; nh < 2; nh++)
                        ldmatrix_x4(bf[nxt][nh][0], bf[nxt][nh][1], bf[nxt][nh][2], bf[nxt][nh][3],
                                    bAddr + (uint32_t)(nh * 16 * 128) + bcol);
                }
#pragma unroll
                for (int mt = 0; mt < 4; mt++)
#pragma unroll
                    for (int nt = 0; nt < 4; nt++) {
                        const int nh = nt >> 1, sub = nt & 1;
                        mma_s8(acc[mt][nt][0], acc[mt][nt][1], acc[mt][nt][2], acc[mt][nt][3],
                               af[cur][mt][0], af[cur][mt][1], af[cur][mt][2], af[cur][mt][3],
                               bf[cur][nh][sub], bf[cur][nh][sub + 2]);
                    }
            }

            __syncwarp();
            if (l == 0) mbar_arrive(sbase + 16 * slot + 8);   // release stage

            const int kn = k + 2;
            if (kn < NK) {   // refill (after compute so tensor pipe stays fed)
                MBAR_WAIT(sbase + 16 * fslot + 8, (uint32_t)fpar);
                fill_stage(sbase, fslot, kn, tid, gA, gB);
                cp_async_mbar_arrive(sbase + 16 * fslot);
                if (++fslot == STAGES) { fslot = 0; fpar ^= 1; }
            }
            if (++slot == STAGES) { slot = 0; cpar ^= 1; }
        }

        // epilogue
        const float alpha = g_alpha;
        const int row_base = m0 + (l >> 2);
        const int col_base = n0 + warp_n * 32 + (l & 3) * 2;
#pragma unroll
        for (int nt = 0; nt < 4; nt++) {
            const int col = col_base + nt * 8;
            const float2 b2 = *reinterpret_cast<const float2*>(bias + col);
#pragma unroll
            for (int mt = 0; mt < 4; mt++) {
                const int r0 = row_base + mt * 16;
                float2 v0, v1;
                v0.x = __fadd_rn(__fmul_rn(__int2float_rn(acc[mt][nt][0]), alpha), b2.x);
                v0.y = __fadd_rn(__fmul_rn(__int2float_rn(acc[mt][nt][1]), alpha), b2.y);
                v1.x = __fadd_rn(__fmul_rn(__int2float_rn(acc[mt][nt][2]), alpha), b2.x);
                v1.y = __fadd_rn(__fmul_rn(__int2float_rn(acc[mt][nt][3]), alpha), b2.y);
                *reinterpret_cast<float2*>(out + (size_t)r0 * OUT_F + col) = v0;
                *reinterpret_cast<float2*>(out + (size_t)(r0 + 8) * OUT_F + col) = v1;
            }
        }
    } else {
        // ---------------- dp4a warps: rows 64..127 (16 per warp), all 128 cols ----------------
        const int dw = wid - 4;                   // 0..3
        const int arow0 = 64 + DROWS * dw;        // (arow0 & 7) == 0

        int acc[DROWS][4];
#pragma unroll
        for (int i = 0; i < DROWS; i++)
#pragma unroll
            for (int j = 0; j < 4; j++) acc[i][j] = 0;

        const uint32_t bswz = (uint32_t)((l & 7) * 16);

        int slot = 0, cpar = 0;

        for (int k = 0; k < NK; k++) {
            MBAR_WAIT(sbase + 16 * slot, (uint32_t)cpar);   // stage data ready

            const char* sAp = smem + SMEM_TILE0 + slot * STAGE_BYTES;
            const char* sBp = sAp + A_STAGE_BYTES;
            const char* aRow = sAp + arow0 * 128;

#pragma unroll 2
            for (int k16 = 0; k16 < BK / 16; k16++) {
                const uint32_t kb16 = (uint32_t)(k16 * 16);
                int4 b4[4];
#pragma unroll
                for (int j = 0; j < 4; j++) {
                    const int brow = l + 32 * j;
                    b4[j] = *reinterpret_cast<const int4*>(sBp + brow * 128 + (kb16 ^ bswz));
                }
#pragma unroll
                for (int i = 0; i < DROWS; i++) {
                    const int4 a4 = *reinterpret_cast<const int4*>(
                        aRow + i * 128 + (kb16 ^ (uint32_t)((i & 7) * 16)));
                    const int* a = reinterpret_cast<const int*>(&a4);
#pragma unroll
                    for (int k4 = 0; k4 < 4; k4++) {
                        acc[i][0] = __dp4a(a[k4], reinterpret_cast<const int*>(&b4[0])[k4], acc[i][0]);
                        acc[i][1] = __dp4a(a[k4], reinterpret_cast<const int*>(&b4[1])[k4], acc[i][1]);
                        acc[i][2] = __dp4a(a[k4], reinterpret_cast<const int*>(&b4[2])[k4], acc[i][2]);
                        acc[i][3] = __dp4a(a[k4], reinterpret_cast<const int*>(&b4[3])[k4], acc[i][3]);
                    }
                }
            }

            __syncwarp();
            if (l == 0) mbar_arrive(sbase + 16 * slot + 8);   // release stage
            if (++slot == STAGES) { slot = 0; cpar ^= 1; }
        }

        // epilogue
        const float alpha = g_alpha;
#pragma unroll
        for (int j = 0; j < 4; j++) {
            const int col = n0 + l + 32 * j;
            const float bj = bias[col];
#pragma unroll
            for (int i = 0; i < DROWS; i++) {
                const int row = m0 + arow0 + i;
                out[(size_t)row * OUT_F + col] =
                    __fadd_rn(__fmul_rn(__int2float_rn(acc[i][j]), alpha), bj);
            }
        }
    }
}

// ---------------- launch ----------------
extern "C" void kernel_launch(void* const* d_in, const int* in_sizes, int n_in,
                              void* d_out, int out_size) {
    const float* x    = (const float*)d_in[0];
    const float* w    = (const float*)d_in[1];
    const float* bias = (const float*)d_in[2];
    float* out = (float*)d_out;

    reduce_partial_kernel<<<RED_BLOCKS, 256>>>(x, w);
    quantize_kernel<<<2048, 256>>>((const float4*)x, (const float4*)w);

    cudaFuncSetAttribute(gemm_kernel, cudaFuncAttributeMaxDynamicSharedMemorySize, SMEM_TOTAL);
    dim3 grid(OUT_F / BN, M_TOTAL / BM);
    gemm_kernel<<<grid, THREADS, SMEM_TOTAL>>>(bias, out);
}